// round 4
// baseline (speedup 1.0000x reference)
#include <cuda_runtime.h>
#include <cstdint>
#include <cstddef>

// BioConvolution: 256 independent GEMMs  C_l[64,128] = A_l[64,1024] * B_l[1024,128]
//   A_l[m][k] = X[m, r*4+i, c*4+j, ch]  (k = i*256+j*64+ch, l = r*16+c)
//   B_l[k][f] = filters[l*131072 + k*128 + f]
//   out[(m*256+l)*128+f] = relu(C + bias[f])
//
// fp16 tensor path (mma.m16n8k16 + ldmatrix, sm_80-portable PTX; fp16 has the
// same 10-bit mantissa as tf32, fp32 accumulate -> rel_err ~3e-4).
// f32->f16 conversion happens ONCE per element in the loader (LDG->cvt->STS),
// K chunk = 64 floats (one (i,j) cell), 2 smem stages, 1 sync/chunk,
// loads pipelined 2 chunks ahead through a 24-register buffer.

namespace {

constexpr int NST = 16;           // K chunks of 64
constexpr int AH  = 72;           // A smem stride (halves): 144B, ldmatrix conflict-free
constexpr int BH  = 136;          // B smem stride (halves): 272B, conflict-free
constexpr int TA  = 64 * AH;      // 4608 halves
constexpr int TB  = 64 * BH;      // 8704 halves
constexpr int STG = TA + TB;      // halves per stage
constexpr int SMEM_BYTES = 2 * STG * 2;  // 53248 B -> 2 CTAs/SM easily

__device__ __forceinline__ uint32_t smem_u32(const void* p) {
    return static_cast<uint32_t>(__cvta_generic_to_shared(p));
}
__device__ __forceinline__ uint32_t pack_h2(float lo, float hi) {
    uint32_t d;
    asm("cvt.rn.f16x2.f32 %0, %1, %2;" : "=r"(d) : "f"(hi), "f"(lo));
    return d;
}
__device__ __forceinline__ void sts128(uint32_t a, uint32_t x, uint32_t y,
                                       uint32_t z, uint32_t w) {
    asm volatile("st.shared.v4.b32 [%0], {%1,%2,%3,%4};"
                 :: "r"(a), "r"(x), "r"(y), "r"(z), "r"(w));
}
__device__ __forceinline__ void ldmx4(uint32_t* r, uint32_t a) {
    asm volatile("ldmatrix.sync.aligned.m8n8.x4.shared.b16 {%0,%1,%2,%3}, [%4];"
                 : "=r"(r[0]), "=r"(r[1]), "=r"(r[2]), "=r"(r[3]) : "r"(a));
}
__device__ __forceinline__ void ldmx4t(uint32_t* r, uint32_t a) {
    asm volatile("ldmatrix.sync.aligned.m8n8.x4.trans.shared.b16 {%0,%1,%2,%3}, [%4];"
                 : "=r"(r[0]), "=r"(r[1]), "=r"(r[2]), "=r"(r[3]) : "r"(a));
}
__device__ __forceinline__ void mma_f16(float* c, const uint32_t* a, const uint32_t* b) {
    asm volatile(
        "mma.sync.aligned.m16n8k16.row.col.f32.f16.f16.f32 "
        "{%0,%1,%2,%3}, {%4,%5,%6,%7}, {%8,%9}, {%0,%1,%2,%3};"
        : "+f"(c[0]), "+f"(c[1]), "+f"(c[2]), "+f"(c[3])
        : "r"(a[0]), "r"(a[1]), "r"(a[2]), "r"(a[3]), "r"(b[0]), "r"(b[1]));
}

__global__ __launch_bounds__(256, 2)
void bioconv_f16_kernel(const float* __restrict__ X,
                        const float* __restrict__ filt,
                        const float* __restrict__ bias,
                        float* __restrict__ out) {
    extern __shared__ __align__(16) char smem[];
    const uint32_t sb = smem_u32(smem);

    const int tid = threadIdx.x;
    const int l   = blockIdx.x;
    const int r   = l >> 4;
    const int cc  = l & 15;

    // ---- loader mapping ----
    // A chunk (i,j): 64 rows (m) x 64 floats (ch). thread: m=tid>>2, 16 floats.
    const int am = tid >> 2, aq = tid & 3;
    // B chunk: 64 k-rows x 128 floats. thread: row=tid&63, 32 floats.
    const int bk = tid & 63, bq = tid >> 6;
    const float* gA0 = X + (size_t)am * 262144 + r * 16384 + cc * 256 + aq * 16;
    const float* gB0 = filt + (size_t)l * 131072 + (size_t)bk * 128 + bq * 32;

    const uint32_t a_sts = (am * AH + aq * 16) * 2;
    const uint32_t b_sts = TA * 2 + (bk * BH + bq * 32) * 2;

    // ---- compute mapping: 8 warps, 2(M) x 4(N), warp tile 32x32 ----
    const int lane = tid & 31;
    const int wid  = tid >> 5;
    const int wm   = wid >> 2;
    const int wn   = wid & 3;
    const int g    = lane >> 2;
    const int t4   = lane & 3;

    // ldmatrix lane addresses (offsets within a stage, bytes)
    const uint32_t a_off = ((wm * 32 + (lane & 15)) * AH + (lane >> 4) * 8) * 2;
    const uint32_t b_off = TA * 2 +
        ((lane & 15) * BH + wn * 32 + ((lane >> 4) & 1) * 8) * 2;

    float acc[2][4][4];
#pragma unroll
    for (int i = 0; i < 2; ++i)
#pragma unroll
        for (int j = 0; j < 4; ++j)
#pragma unroll
            for (int k = 0; k < 4; ++k) acc[i][j][k] = 0.f;

    uint32_t buf[24];

    auto ldcvt = [&](int t) {
        const float* ga = gA0 + (t >> 2) * 4096 + (t & 3) * 64;
#pragma unroll
        for (int i = 0; i < 4; ++i) {
            const float4 v = *reinterpret_cast<const float4*>(ga + i * 4);
            buf[i * 2]     = pack_h2(v.x, v.y);
            buf[i * 2 + 1] = pack_h2(v.z, v.w);
        }
        const float* gb = gB0 + (size_t)t * 8192;
#pragma unroll
        for (int i = 0; i < 8; ++i) {
            const float4 v = *reinterpret_cast<const float4*>(gb + i * 4);
            buf[8 + i * 2] = pack_h2(v.x, v.y);
            buf[9 + i * 2] = pack_h2(v.z, v.w);
        }
    };
    auto stsbuf = [&](int s) {
        const uint32_t base = sb + s * (STG * 2);
        sts128(base + a_sts,      buf[0], buf[1], buf[2], buf[3]);
        sts128(base + a_sts + 16, buf[4], buf[5], buf[6], buf[7]);
#pragma unroll
        for (int i = 0; i < 4; ++i)
            sts128(base + b_sts + i * 16,
                   buf[8 + i * 4], buf[9 + i * 4], buf[10 + i * 4], buf[11 + i * 4]);
    };

    ldcvt(0);
    stsbuf(0);
    ldcvt(1);
    __syncthreads();

    for (int t = 0; t < NST; ++t) {
        // release next stage early: STS(t+1), then prefetch LDG(t+2),
        // then compute(t) hides the DRAM latency.
        if (t + 1 < NST) stsbuf((t + 1) & 1);
        if (t + 2 < NST) ldcvt(t + 2);

        const uint32_t base = sb + (t & 1) * (STG * 2);
        const uint32_t aa = base + a_off;
        const uint32_t bb = base + b_off;

#pragma unroll
        for (int kh = 0; kh < 4; ++kh) {
            uint32_t A0[4], A1[4], B0[4], B1[4];
            ldmx4(A0, aa + kh * 32);                 // rows wm*32+0..15
            ldmx4(A1, aa + 16 * AH * 2 + kh * 32);   // rows wm*32+16..31
            ldmx4t(B0, bb + kh * (16 * BH * 2));     // n 0..15 of warp tile
            ldmx4t(B1, bb + 32 + kh * (16 * BH * 2)); // n 16..31

            mma_f16(acc[0][0], A0, &B0[0]);
            mma_f16(acc[0][1], A0, &B0[2]);
            mma_f16(acc[0][2], A0, &B1[0]);
            mma_f16(acc[0][3], A0, &B1[2]);
            mma_f16(acc[1][0], A1, &B0[0]);
            mma_f16(acc[1][1], A1, &B0[2]);
            mma_f16(acc[1][2], A1, &B1[0]);
            mma_f16(acc[1][3], A1, &B1[2]);
        }
        if (t + 1 < NST) __syncthreads();
    }

    // ---- epilogue: bias + relu ----
#pragma unroll
    for (int nt = 0; nt < 4; ++nt) {
        const int n0 = wn * 32 + nt * 8 + t4 * 2;
        const float2 bv = *reinterpret_cast<const float2*>(bias + n0);
#pragma unroll
        for (int mt = 0; mt < 2; ++mt) {
            const int m = wm * 32 + mt * 16 + g;
            float2 o0, o1;
            o0.x = fmaxf(acc[mt][nt][0] + bv.x, 0.f);
            o0.y = fmaxf(acc[mt][nt][1] + bv.y, 0.f);
            o1.x = fmaxf(acc[mt][nt][2] + bv.x, 0.f);
            o1.y = fmaxf(acc[mt][nt][3] + bv.y, 0.f);
            *reinterpret_cast<float2*>(out + ((size_t)m * 256 + l) * 128 + n0) = o0;
            *reinterpret_cast<float2*>(out + ((size_t)(m + 8) * 256 + l) * 128 + n0) = o1;
        }
    }
}

}  // namespace

extern "C" void kernel_launch(void* const* d_in, const int* in_sizes, int n_in,
                              void* d_out, int out_size) {
    const float* X    = (const float*)d_in[0];
    const float* filt = (const float*)d_in[1];
    const float* bias = (const float*)d_in[2];
    float* out        = (float*)d_out;

    cudaFuncSetAttribute(bioconv_f16_kernel,
                         cudaFuncAttributeMaxDynamicSharedMemorySize, SMEM_BYTES);
    bioconv_f16_kernel<<<256, 256, SMEM_BYTES>>>(X, filt, bias, out);
}